// round 12
// baseline (speedup 1.0000x reference)
#include <cuda_runtime.h>
#include <cuda_bf16.h>
#include <cstdint>

#define B_   64
#define T_   512
#define IN_  1024
#define H_   256
#define G4   1024
#define NC_  8

typedef unsigned long long ull;

// ---- scratch (device globals; no allocation allowed) ----
__device__ float    g_xg[B_ * T_ * G4];    // gate preactivations fp32
__device__ uint32_t g_as[B_ * T_ * IN_];   // split-packed x
__device__ uint32_t g_hs1[B_ * T_ * H_];   // split-packed h (layer outs)
__device__ uint32_t g_hs2[B_ * T_ * H_];
__device__ uint32_t g_ws[G4 * IN_];        // split-packed Wih (reused per layer)

__device__ __forceinline__ uint32_t smem_u32(const void* p) {
    uint32_t a;
    asm("{ .reg .u64 t; cvta.to.shared.u64 t, %1; cvt.u32.u64 %0, t; }" : "=r"(a) : "l"(p));
    return a;
}
__device__ __forceinline__ uint32_t prmt(uint32_t a, uint32_t b, uint32_t s) {
    uint32_t r; asm("prmt.b32 %0,%1,%2,%3;" : "=r"(r) : "r"(a), "r"(b), "r"(s)); return r;
}
__device__ __forceinline__ uint32_t ps32(float f) {   // packed split bf16
    __nv_bfloat16 h = __float2bfloat16(f);
    __nv_bfloat16 l = __float2bfloat16(f - __bfloat162float(h));
    return (uint32_t)__bfloat16_as_ushort(h) | ((uint32_t)__bfloat16_as_ushort(l) << 16);
}
__device__ __forceinline__ float ups(uint32_t v) {
    return __bfloat162float(__ushort_as_bfloat16((unsigned short)(v & 0xFFFF)))
         + __bfloat162float(__ushort_as_bfloat16((unsigned short)(v >> 16)));
}

// ---- MUFU-free exp / rcp ----
__device__ __forceinline__ float fexp(float x) {
    float z = x * 1.4426950408889634f;
    float t = z + 12582912.0f;
    int n = __float_as_int(t) - 0x4B400000;
    float f = z - (t - 12582912.0f);
    float p = 1.5403530394e-4f;
    p = fmaf(p, f, 1.3333558147e-3f);
    p = fmaf(p, f, 9.6181291891e-3f);
    p = fmaf(p, f, 5.5504108665e-2f);
    p = fmaf(p, f, 2.4022650696e-1f);
    p = fmaf(p, f, 6.9314718056e-1f);
    p = fmaf(p, f, 1.0f);
    return __int_as_float(__float_as_int(p) + (n << 23));
}
__device__ __forceinline__ float frcp(float d) {
    float r = __int_as_float(0x7EF311C3 - __float_as_int(d));
    r = r * fmaf(-d, r, 2.0f);
    r = r * fmaf(-d, r, 2.0f);
    r = r * fmaf(-d, r, 2.0f);
    return r;
}
__device__ __forceinline__ float sigm_f(float x) {
    float xx = fminf(fmaxf(x, -15.f), 15.f);
    return frcp(1.0f + fexp(-xx));
}
__device__ __forceinline__ float tanh_f(float x) {
    float xx = fminf(fmaxf(x, -8.f), 8.f);
    return fmaf(-2.0f, frcp(fexp(2.0f * xx) + 1.0f), 1.0f);
}

__device__ __forceinline__ void mma16816(float* d, const uint32_t* a,
                                         uint32_t b0, uint32_t b1) {
    asm volatile(
        "mma.sync.aligned.m16n8k16.row.col.f32.bf16.bf16.f32 "
        "{%0,%1,%2,%3}, {%4,%5,%6,%7}, {%8,%9}, {%0,%1,%2,%3};"
        : "+f"(d[0]), "+f"(d[1]), "+f"(d[2]), "+f"(d[3])
        : "r"(a[0]), "r"(a[1]), "r"(a[2]), "r"(a[3]), "r"(b0), "r"(b1));
}
__device__ __forceinline__ void ldsm4(uint32_t* r, uint32_t addr) {
    asm volatile("ldmatrix.sync.aligned.m8n8.x4.shared.b16 {%0,%1,%2,%3}, [%4];"
                 : "=r"(r[0]), "=r"(r[1]), "=r"(r[2]), "=r"(r[3]) : "r"(addr));
}
__device__ __forceinline__ void sp2(float2 f, uint32_t& hi, uint32_t& lo) {
    __nv_bfloat162 h = __float22bfloat162_rn(f);
    float2 hf = __bfloat1622float2(h);
    __nv_bfloat162 l = __float22bfloat162_rn(make_float2(f.x - hf.x, f.y - hf.y));
    hi = *(uint32_t*)&h; lo = *(uint32_t*)&l;
}
__device__ __forceinline__ void mbar_wait_acqc(uint32_t a, int ph) {
    asm volatile("{\n\t.reg .pred P;\n\tW%=:\n\t"
                 "mbarrier.try_wait.parity.acquire.cluster.shared::cta.b64 P, [%0], %1;\n\t"
                 "@!P bra W%=;\n\t}" :: "r"(a), "r"(ph) : "memory");
}

// ============================================================================
// split pre-pass: fp32 -> packed split bf16 (hi | lo<<16)
// ============================================================================
__global__ __launch_bounds__(256) void split_ps(const float* __restrict__ in,
                                                uint32_t* __restrict__ out, int n4) {
    int i = blockIdx.x * 256 + threadIdx.x;
    if (i < n4) {
        float4 v = ((const float4*)in)[i];
        uint4 o;
        o.x = ps32(v.x); o.y = ps32(v.y); o.z = ps32(v.z); o.w = ps32(v.w);
        ((uint4*)out)[i] = o;
    }
}

// ============================================================================
// Tensor GEMM: C[M,1024] = A[M,K](ps32) @ W[1024,K](ps32)^T + bias
// 128x128x16 tiles, 8 warps x (32x64). SMEM 16B-chunk swizzle:
// half' = half ^ ((row>>2)&1)  -> ldmatrix & STS both conflict-free.
// ============================================================================
__global__ __launch_bounds__(256) void gemm_tc(
    const uint32_t* __restrict__ A, const uint32_t* __restrict__ W,
    const float* __restrict__ bias, float* __restrict__ C, int K)
{
    __shared__ __align__(16) unsigned short sm[2][4][128 * 16];
    int t = threadIdx.x, lane = t & 31, w = t >> 5;
    int m0 = blockIdx.y * 128, n0 = blockIdx.x * 128;
    int mi = w & 3, nj = w >> 2;
    int K16 = K / 16;

    int row = t >> 1, half = t & 1;
    const uint32_t* gA = A + (ull)(m0 + row) * K + half * 8;
    const uint32_t* gW = W + (ull)(n0 + row) * K + half * 8;

    uint4 ra0, ra1, rw0, rw1;
    auto LDG = [&](int kk) {
        const uint32_t* pa = gA + kk * 16;
        const uint32_t* pw = gW + kk * 16;
        ra0 = *(const uint4*)pa; ra1 = *(const uint4*)(pa + 4);
        rw0 = *(const uint4*)pw; rw1 = *(const uint4*)(pw + 4);
    };
    auto STS = [&](int st) {
        uint32_t p[8] = { ra0.x, ra0.y, ra0.z, ra0.w, ra1.x, ra1.y, ra1.z, ra1.w };
        uint32_t q[8] = { rw0.x, rw0.y, rw0.z, rw0.w, rw1.x, rw1.y, rw1.z, rw1.w };
        uint4 ahi, alo, whi, wlo;
        ahi.x = prmt(p[0], p[1], 0x5410); alo.x = prmt(p[0], p[1], 0x7632);
        ahi.y = prmt(p[2], p[3], 0x5410); alo.y = prmt(p[2], p[3], 0x7632);
        ahi.z = prmt(p[4], p[5], 0x5410); alo.z = prmt(p[4], p[5], 0x7632);
        ahi.w = prmt(p[6], p[7], 0x5410); alo.w = prmt(p[6], p[7], 0x7632);
        whi.x = prmt(q[0], q[1], 0x5410); wlo.x = prmt(q[0], q[1], 0x7632);
        whi.y = prmt(q[2], q[3], 0x5410); wlo.y = prmt(q[2], q[3], 0x7632);
        whi.z = prmt(q[4], q[5], 0x5410); wlo.z = prmt(q[4], q[5], 0x7632);
        whi.w = prmt(q[6], q[7], 0x5410); wlo.w = prmt(q[6], q[7], 0x7632);
        int o = row * 16 + (half ^ ((row >> 2) & 1)) * 8;   // swizzled chunk
        *(uint4*)&sm[st][0][o] = ahi; *(uint4*)&sm[st][1][o] = alo;
        *(uint4*)&sm[st][2][o] = whi; *(uint4*)&sm[st][3][o] = wlo;
    };

    float acc[2][8][4];
#pragma unroll
    for (int s = 0; s < 2; s++)
#pragma unroll
        for (int nt = 0; nt < 8; nt++)
#pragma unroll
            for (int j = 0; j < 4; j++) acc[s][nt][j] = 0.f;

    uint32_t smb = smem_u32(sm);
    int mt = lane >> 3, rr = lane & 7;

    LDG(0); STS(0);
    __syncthreads();

    for (int kk = 0; kk < K16; kk++) {
        if (kk + 1 < K16) LDG(kk + 1);
        int st = kk & 1;
        uint32_t ah[2][4], al[2][4], bh[8][2], bl[8][2];
#pragma unroll
        for (int s = 0; s < 2; s++) {
            int arow = mi * 32 + s * 16 + (mt & 1) * 8 + rr;
            uint32_t aoff = (uint32_t)(((st * 4 + 0) * 2048 +
                arow * 16 + ((mt >> 1) ^ ((arow >> 2) & 1)) * 8) * 2);
            ldsm4(ah[s], smb + aoff);
            ldsm4(al[s], smb + aoff + 4096);
        }
#pragma unroll
        for (int np = 0; np < 4; np++) {
            int brow = nj * 64 + (np * 2 + (mt >> 1)) * 8 + rr;
            uint32_t boff = (uint32_t)(((st * 4 + 2) * 2048 +
                brow * 16 + ((mt & 1) ^ ((brow >> 2) & 1)) * 8) * 2);
            uint32_t r[4];
            ldsm4(r, smb + boff);
            bh[2 * np][0] = r[0]; bh[2 * np][1] = r[1];
            bh[2 * np + 1][0] = r[2]; bh[2 * np + 1][1] = r[3];
            ldsm4(r, smb + boff + 4096);
            bl[2 * np][0] = r[0]; bl[2 * np][1] = r[1];
            bl[2 * np + 1][0] = r[2]; bl[2 * np + 1][1] = r[3];
        }
#pragma unroll
        for (int s = 0; s < 2; s++)
#pragma unroll
            for (int nt = 0; nt < 8; nt++) {
                mma16816(acc[s][nt], ah[s], bh[nt][0], bh[nt][1]);
                mma16816(acc[s][nt], ah[s], bl[nt][0], bl[nt][1]);
                mma16816(acc[s][nt], al[s], bh[nt][0], bh[nt][1]);
            }
        if (kk + 1 < K16) STS((kk + 1) & 1);
        __syncthreads();
    }

#pragma unroll
    for (int s = 0; s < 2; s++) {
        int m = m0 + mi * 32 + s * 16 + (lane >> 2);
#pragma unroll
        for (int nt = 0; nt < 8; nt++) {
            int n = n0 + nj * 64 + nt * 8 + 2 * (lane & 3);
            float b0v = bias[n], b1v = bias[n + 1];
            *(float2*)&C[(ull)m * G4 + n] =
                make_float2(acc[s][nt][0] + b0v, acc[s][nt][1] + b1v);
            *(float2*)&C[(ull)(m + 8) * G4 + n] =
                make_float2(acc[s][nt][2] + b0v, acc[s][nt][3] + b1v);
        }
    }
}

// ============================================================================
// LSTM recurrence, 2-group pipelined (mma.sync split-bf16, direct remote frags)
// 4 clusters x 8 CTAs x 256 thr; cluster owns 16 batches = 2 groups of 8.
// Group phases are interleaved so each group's DSMEM exchange latency is
// hidden behind the other group's compute.
// ============================================================================
#define RT_CL 8

__global__ __launch_bounds__(256, 1) __cluster_dims__(RT_CL, 1, 1)
void lstm_recur2(const float* __restrict__ xg, const float* __restrict__ Whh,
                 uint32_t* __restrict__ hs)
{
    __shared__ ull Bfrag[2][2][2][512];        // [grp][parity][hi/lo][kt*32+4b+cq]
    __shared__ float PRE[8 * 132];             // [b][ri] pitch 132
    __shared__ unsigned short stg2[2][8][32];  // [hi/lo][b][u]
    __shared__ __align__(8) ull bars[4];       // [grp*2 + parity]

    int t = threadIdx.x;
    int w = t >> 5, lane = t & 31;
    uint32_t rank;
    asm("mov.u32 %0, %%cluster_ctarank;" : "=r"(rank));
    int b0 = (blockIdx.x / RT_CL) * 16;

    uint32_t barsb = smem_u32(bars);
    if (t == 0) {
#pragma unroll
        for (int i = 0; i < 4; i++)
            asm volatile("mbarrier.init.shared.b64 [%0], %1;"
                         :: "r"(barsb + 8 * i), "r"(256) : "memory");
    }

    // A fragments (hi/lo) in registers — shared by both groups
    int r0 = 16 * w + (lane >> 2);
    int k0 = (lane & 3) * 2;
    uint32_t ahi[16][4], alo[16][4];
    {
        int g0 = r0 & 3, u0 = r0 >> 2;
        const float* W0 = Whh + (ull)(256 * g0 + 32 * (int)rank + u0) * H_;
        const float* W1 = W0 + 2 * H_;
#pragma unroll
        for (int kt = 0; kt < 16; kt++) {
            sp2(*(const float2*)(W0 + k0 + 16 * kt),     ahi[kt][0], alo[kt][0]);
            sp2(*(const float2*)(W1 + k0 + 16 * kt),     ahi[kt][1], alo[kt][1]);
            sp2(*(const float2*)(W0 + k0 + 16 * kt + 8), ahi[kt][2], alo[kt][2]);
            sp2(*(const float2*)(W1 + k0 + 16 * kt + 8), ahi[kt][3], alo[kt][3]);
        }
    }
    for (int i = t; i < 4096; i += 256) ((ull*)Bfrag)[i] = 0ull;
    __syncthreads();
    asm volatile("barrier.cluster.arrive.aligned;" ::: "memory");
    asm volatile("barrier.cluster.wait.aligned;" ::: "memory");

    // pusher identity
    int tgt = t >> 5;
    int pb = t & 7, pcq = (t >> 3) & 3;
    uint32_t rBf, rBar;
    asm("mapa.shared::cluster.u32 %0, %1, %2;" : "=r"(rBf)  : "r"(smem_u32(Bfrag)), "r"(tgt));
    asm("mapa.shared::cluster.u32 %0, %1, %2;" : "=r"(rBar) : "r"(barsb),           "r"(tgt));

    float c_reg[2] = {0.f, 0.f};
    int jown = 32 * (int)rank + lane;

    int grow0 = 256 * (r0 & 3) + 32 * (int)rank + (r0 >> 2);
    const float* xp[2][2];
#pragma unroll
    for (int g = 0; g < 2; g++) {
        xp[g][0] = xg + (ull)(b0 + 8 * g + k0) * T_ * G4 + grow0;
        xp[g][1] = xg + (ull)(b0 + 8 * g + k0 + 1) * T_ * G4 + grow0;
    }
    int ph[4] = {0, 0, 0, 0};

    for (int ts = 0; ts < T_; ts++) {
        int p = ts & 1;
#pragma unroll
        for (int g = 0; g < 2; g++) {
            if (ts) {
                int bidx = g * 2 + p;
                mbar_wait_acqc(barsb + 8 * bidx, ph[bidx]);
                ph[bidx] ^= 1;
            }
            float x00 = xp[g][0][0], x02 = xp[g][0][2];
            float x01 = xp[g][1][0], x03 = xp[g][1][2];
            xp[g][0] += G4; xp[g][1] += G4;

            float aA[4] = {0, 0, 0, 0}, aB[4] = {0, 0, 0, 0}, aC[4] = {0, 0, 0, 0};
#pragma unroll
            for (int kt = 0; kt < 16; kt++) {
                ull bh = Bfrag[g][p][0][kt * 32 + lane];
                ull bl = Bfrag[g][p][1][kt * 32 + lane];
                uint32_t bh0 = (uint32_t)bh, bh1 = (uint32_t)(bh >> 32);
                uint32_t bl0 = (uint32_t)bl, bl1 = (uint32_t)(bl >> 32);
                mma16816(aA, ahi[kt], bh0, bh1);
                mma16816(aB, ahi[kt], bl0, bl1);
                mma16816(aC, alo[kt], bh0, bh1);
            }
            PRE[(k0)     * 132 + r0]     = aA[0] + aB[0] + aC[0] + x00;
            PRE[(k0 + 1) * 132 + r0]     = aA[1] + aB[1] + aC[1] + x01;
            PRE[(k0)     * 132 + r0 + 8] = aA[2] + aB[2] + aC[2] + x02;
            PRE[(k0 + 1) * 132 + r0 + 8] = aA[3] + aB[3] + aC[3] + x03;
            __syncthreads();

            {   // gates: thread = (u=lane, b=w) of this group
                float4 v = *(const float4*)&PRE[w * 132 + 4 * lane];
                float iv = sigm_f(v.x), fv = sigm_f(v.y), ov = sigm_f(v.w);
                float gv = tanh_f(v.z);
                float c = fv * c_reg[g] + iv * gv;
                c_reg[g] = c;
                float h = ov * tanh_f(c);
                __nv_bfloat16 hh = __float2bfloat16(h);
                __nv_bfloat16 hl = __float2bfloat16(h - __bfloat162float(hh));
                unsigned short uh = __bfloat16_as_ushort(hh);
                unsigned short ul = __bfloat16_as_ushort(hl);
                hs[((ull)(b0 + 8 * g + w) * T_ + ts) * H_ + jown] =
                    (uint32_t)uh | ((uint32_t)ul << 16);
                stg2[0][w][lane] = uh;
                stg2[1][w][lane] = ul;
            }
            __syncthreads();

            {   // push direct-fragment u64s into target CTA's Bfrag[g][p^1]
                uint32_t base = rBf + (uint32_t)(g * 16384 + (p ^ 1) * 8192);
#pragma unroll
                for (int arr = 0; arr < 2; arr++)
#pragma unroll
                    for (int tau = 0; tau < 2; tau++) {
                        uint32_t lo32 = *(const uint32_t*)&stg2[arr][pb][16 * tau + 2 * pcq];
                        uint32_t hi32 = *(const uint32_t*)&stg2[arr][pb][16 * tau + 2 * pcq + 8];
                        ull v = (ull)lo32 | ((ull)hi32 << 32);
                        uint32_t idx = (uint32_t)((2 * (int)rank + tau) * 32 + 4 * pb + pcq);
                        uint32_t dst = base + (uint32_t)(arr * 4096) + idx * 8;
                        asm volatile("st.shared::cluster.u64 [%0], %1;" :: "r"(dst), "l"(v) : "memory");
                    }
                asm volatile("mbarrier.arrive.release.cluster.shared::cluster.b64 _, [%0];"
                             :: "r"(rBar + (uint32_t)((g * 2 + (p ^ 1)) * 8)) : "memory");
            }
        }
    }

    asm volatile("barrier.cluster.arrive.aligned;" ::: "memory");
    asm volatile("barrier.cluster.wait.aligned;" ::: "memory");
}

// ============================================================================
// FC head (reads packed h)
// ============================================================================
__global__ __launch_bounds__(128) void fc_head(
    const uint32_t* __restrict__ hall, const float* __restrict__ W1,
    const float* __restrict__ b1,     const float* __restrict__ W2,
    const float* __restrict__ b2,     float* __restrict__ out)
{
    __shared__ float hl[H_];
    __shared__ float z[128];
    int b = blockIdx.x, t = threadIdx.x;
    hl[t]       = ups(hall[((ull)b * T_ + (T_ - 1)) * H_ + t]);
    hl[t + 128] = ups(hall[((ull)b * T_ + (T_ - 1)) * H_ + t + 128]);
    __syncthreads();
    float acc = b1[t];
    const float* ww = W1 + t * H_;
#pragma unroll 8
    for (int k = 0; k < H_; k++) acc += ww[k] * hl[k];
    z[t] = fmaxf(acc, 0.f);
    __syncthreads();
    if (t < NC_) {
        float a2 = b2[t];
        const float* w2 = W2 + t * 128;
#pragma unroll 8
        for (int k = 0; k < 128; k++) a2 += w2[k] * z[k];
        out[b * NC_ + t] = a2;
    }
}

// ============================================================================
extern "C" void kernel_launch(void* const* d_in, const int* in_sizes, int n_in,
                              void* d_out, int out_size)
{
    const float* x    = (const float*)d_in[0];
    const float* Wih0 = (const float*)d_in[1];
    const float* Whh0 = (const float*)d_in[2];
    const float* b0   = (const float*)d_in[3];
    const float* Wih1 = (const float*)d_in[4];
    const float* Whh1 = (const float*)d_in[5];
    const float* b1   = (const float*)d_in[6];
    const float* Wih2 = (const float*)d_in[7];
    const float* Whh2 = (const float*)d_in[8];
    const float* b2   = (const float*)d_in[9];
    const float* W1   = (const float*)d_in[10];
    const float* bfc1 = (const float*)d_in[11];
    const float* W2   = (const float*)d_in[12];
    const float* bfc2 = (const float*)d_in[13];
    float* out = (float*)d_out;

    float* xg; uint32_t *as, *hs1, *hs2, *ws;
    cudaGetSymbolAddress((void**)&xg,  g_xg);
    cudaGetSymbolAddress((void**)&as,  g_as);
    cudaGetSymbolAddress((void**)&hs1, g_hs1);
    cudaGetSymbolAddress((void**)&hs2, g_hs2);
    cudaGetSymbolAddress((void**)&ws,  g_ws);

    dim3 ggrd(G4 / 128, (B_ * T_) / 128);   // (8, 256)
    int rgrid = (B_ / 16) * RT_CL;          // 32 CTAs = 4 clusters
    int nx  = B_ * T_ * IN_ / 4;
    int nw0 = G4 * IN_ / 4;
    int nwh = G4 * H_ / 4;

    // layer 0
    split_ps<<<(nx + 255) / 256, 256>>>(x, as, nx);
    split_ps<<<(nw0 + 255) / 256, 256>>>(Wih0, ws, nw0);
    gemm_tc<<<ggrd, 256>>>(as, ws, b0, xg, IN_);
    lstm_recur2<<<rgrid, 256>>>(xg, Whh0, hs1);
    // layer 1
    split_ps<<<(nwh + 255) / 256, 256>>>(Wih1, ws, nwh);
    gemm_tc<<<ggrd, 256>>>(hs1, ws, b1, xg, H_);
    lstm_recur2<<<rgrid, 256>>>(xg, Whh1, hs2);
    // layer 2
    split_ps<<<(nwh + 255) / 256, 256>>>(Wih2, ws, nwh);
    gemm_tc<<<ggrd, 256>>>(hs2, ws, b2, xg, H_);
    lstm_recur2<<<rgrid, 256>>>(xg, Whh2, hs1);
    // head
    fc_head<<<B_, 128>>>(hs1, W1, bfc1, W2, bfc2, out);
}

// round 14
// speedup vs baseline: 1.0500x; 1.0500x over previous
#include <cuda_runtime.h>
#include <cuda_bf16.h>
#include <cstdint>

#define B_   64
#define T_   512
#define IN_  1024
#define H_   256
#define G4   1024
#define NC_  8

typedef unsigned long long ull;

// ---- scratch (device globals; no allocation allowed) ----
__device__ float    g_xg[B_ * T_ * G4];    // gate preactivations fp32
__device__ uint32_t g_as[B_ * T_ * IN_];   // split-packed x
__device__ uint32_t g_hs1[B_ * T_ * H_];   // split-packed h (layer outs)
__device__ uint32_t g_hs2[B_ * T_ * H_];
__device__ uint32_t g_ws[G4 * IN_];        // split-packed Wih (reused per layer)

__device__ __forceinline__ uint32_t smem_u32(const void* p) {
    uint32_t a;
    asm("{ .reg .u64 t; cvta.to.shared.u64 t, %1; cvt.u32.u64 %0, t; }" : "=r"(a) : "l"(p));
    return a;
}
__device__ __forceinline__ uint32_t prmt(uint32_t a, uint32_t b, uint32_t s) {
    uint32_t r; asm("prmt.b32 %0,%1,%2,%3;" : "=r"(r) : "r"(a), "r"(b), "r"(s)); return r;
}
__device__ __forceinline__ uint32_t ps32(float f) {   // packed split bf16
    __nv_bfloat16 h = __float2bfloat16(f);
    __nv_bfloat16 l = __float2bfloat16(f - __bfloat162float(h));
    return (uint32_t)__bfloat16_as_ushort(h) | ((uint32_t)__bfloat16_as_ushort(l) << 16);
}
__device__ __forceinline__ float ups(uint32_t v) {
    return __bfloat162float(__ushort_as_bfloat16((unsigned short)(v & 0xFFFF)))
         + __bfloat162float(__ushort_as_bfloat16((unsigned short)(v >> 16)));
}

// ---- MUFU-free exp / rcp ----
__device__ __forceinline__ float fexp(float x) {
    float z = x * 1.4426950408889634f;
    float t = z + 12582912.0f;
    int n = __float_as_int(t) - 0x4B400000;
    float f = z - (t - 12582912.0f);
    float p = 1.5403530394e-4f;
    p = fmaf(p, f, 1.3333558147e-3f);
    p = fmaf(p, f, 9.6181291891e-3f);
    p = fmaf(p, f, 5.5504108665e-2f);
    p = fmaf(p, f, 2.4022650696e-1f);
    p = fmaf(p, f, 6.9314718056e-1f);
    p = fmaf(p, f, 1.0f);
    return __int_as_float(__float_as_int(p) + (n << 23));
}
__device__ __forceinline__ float frcp(float d) {
    float r = __int_as_float(0x7EF311C3 - __float_as_int(d));
    r = r * fmaf(-d, r, 2.0f);
    r = r * fmaf(-d, r, 2.0f);
    r = r * fmaf(-d, r, 2.0f);
    return r;
}
__device__ __forceinline__ float sigm_f(float x) {
    float xx = fminf(fmaxf(x, -15.f), 15.f);
    return frcp(1.0f + fexp(-xx));
}
__device__ __forceinline__ float tanh_f(float x) {
    float xx = fminf(fmaxf(x, -8.f), 8.f);
    return fmaf(-2.0f, frcp(fexp(2.0f * xx) + 1.0f), 1.0f);
}

__device__ __forceinline__ void mma16816(float* d, const uint32_t* a,
                                         uint32_t b0, uint32_t b1) {
    asm volatile(
        "mma.sync.aligned.m16n8k16.row.col.f32.bf16.bf16.f32 "
        "{%0,%1,%2,%3}, {%4,%5,%6,%7}, {%8,%9}, {%0,%1,%2,%3};"
        : "+f"(d[0]), "+f"(d[1]), "+f"(d[2]), "+f"(d[3])
        : "r"(a[0]), "r"(a[1]), "r"(a[2]), "r"(a[3]), "r"(b0), "r"(b1));
}
__device__ __forceinline__ void ldsm4(uint32_t* r, uint32_t addr) {
    asm volatile("ldmatrix.sync.aligned.m8n8.x4.shared.b16 {%0,%1,%2,%3}, [%4];"
                 : "=r"(r[0]), "=r"(r[1]), "=r"(r[2]), "=r"(r[3]) : "r"(addr));
}
__device__ __forceinline__ void sp2(float2 f, uint32_t& hi, uint32_t& lo) {
    __nv_bfloat162 h = __float22bfloat162_rn(f);
    float2 hf = __bfloat1622float2(h);
    __nv_bfloat162 l = __float22bfloat162_rn(make_float2(f.x - hf.x, f.y - hf.y));
    hi = *(uint32_t*)&h; lo = *(uint32_t*)&l;
}
__device__ __forceinline__ void mbar_wait_acqc(uint32_t a, int ph) {
    asm volatile("{\n\t.reg .pred P;\n\tW%=:\n\t"
                 "mbarrier.try_wait.parity.acquire.cluster.shared::cta.b64 P, [%0], %1;\n\t"
                 "@!P bra W%=;\n\t}" :: "r"(a), "r"(ph) : "memory");
}

// ============================================================================
// split pre-pass: fp32 -> packed split bf16 (hi | lo<<16)
// ============================================================================
__global__ __launch_bounds__(256) void split_ps(const float* __restrict__ in,
                                                uint32_t* __restrict__ out, int n4) {
    int i = blockIdx.x * 256 + threadIdx.x;
    if (i < n4) {
        float4 v = ((const float4*)in)[i];
        uint4 o;
        o.x = ps32(v.x); o.y = ps32(v.y); o.z = ps32(v.z); o.w = ps32(v.w);
        ((uint4*)out)[i] = o;
    }
}

// ============================================================================
// Tensor GEMM (swizzled SMEM, unchanged from R12 — verified correct)
// ============================================================================
__global__ __launch_bounds__(256) void gemm_tc(
    const uint32_t* __restrict__ A, const uint32_t* __restrict__ W,
    const float* __restrict__ bias, float* __restrict__ C, int K)
{
    __shared__ __align__(16) unsigned short sm[2][4][128 * 16];
    int t = threadIdx.x, lane = t & 31, w = t >> 5;
    int m0 = blockIdx.y * 128, n0 = blockIdx.x * 128;
    int mi = w & 3, nj = w >> 2;
    int K16 = K / 16;

    int row = t >> 1, half = t & 1;
    const uint32_t* gA = A + (ull)(m0 + row) * K + half * 8;
    const uint32_t* gW = W + (ull)(n0 + row) * K + half * 8;

    uint4 ra0, ra1, rw0, rw1;
    auto LDG = [&](int kk) {
        const uint32_t* pa = gA + kk * 16;
        const uint32_t* pw = gW + kk * 16;
        ra0 = *(const uint4*)pa; ra1 = *(const uint4*)(pa + 4);
        rw0 = *(const uint4*)pw; rw1 = *(const uint4*)(pw + 4);
    };
    auto STS = [&](int st) {
        uint32_t p[8] = { ra0.x, ra0.y, ra0.z, ra0.w, ra1.x, ra1.y, ra1.z, ra1.w };
        uint32_t q[8] = { rw0.x, rw0.y, rw0.z, rw0.w, rw1.x, rw1.y, rw1.z, rw1.w };
        uint4 ahi, alo, whi, wlo;
        ahi.x = prmt(p[0], p[1], 0x5410); alo.x = prmt(p[0], p[1], 0x7632);
        ahi.y = prmt(p[2], p[3], 0x5410); alo.y = prmt(p[2], p[3], 0x7632);
        ahi.z = prmt(p[4], p[5], 0x5410); alo.z = prmt(p[4], p[5], 0x7632);
        ahi.w = prmt(p[6], p[7], 0x5410); alo.w = prmt(p[6], p[7], 0x7632);
        whi.x = prmt(q[0], q[1], 0x5410); wlo.x = prmt(q[0], q[1], 0x7632);
        whi.y = prmt(q[2], q[3], 0x5410); wlo.y = prmt(q[2], q[3], 0x7632);
        whi.z = prmt(q[4], q[5], 0x5410); wlo.z = prmt(q[4], q[5], 0x7632);
        whi.w = prmt(q[6], q[7], 0x5410); wlo.w = prmt(q[6], q[7], 0x7632);
        int o = row * 16 + (half ^ ((row >> 2) & 1)) * 8;
        *(uint4*)&sm[st][0][o] = ahi; *(uint4*)&sm[st][1][o] = alo;
        *(uint4*)&sm[st][2][o] = whi; *(uint4*)&sm[st][3][o] = wlo;
    };

    float acc[2][8][4];
#pragma unroll
    for (int s = 0; s < 2; s++)
#pragma unroll
        for (int nt = 0; nt < 8; nt++)
#pragma unroll
            for (int j = 0; j < 4; j++) acc[s][nt][j] = 0.f;

    uint32_t smb = smem_u32(sm);
    int mt = lane >> 3, rr = lane & 7;

    LDG(0); STS(0);
    __syncthreads();

    for (int kk = 0; kk < K16; kk++) {
        if (kk + 1 < K16) LDG(kk + 1);
        int st = kk & 1;
        uint32_t ah[2][4], al[2][4], bh[8][2], bl[8][2];
#pragma unroll
        for (int s = 0; s < 2; s++) {
            int arow = mi * 32 + s * 16 + (mt & 1) * 8 + rr;
            uint32_t aoff = (uint32_t)(((st * 4 + 0) * 2048 +
                arow * 16 + ((mt >> 1) ^ ((arow >> 2) & 1)) * 8) * 2);
            ldsm4(ah[s], smb + aoff);
            ldsm4(al[s], smb + aoff + 4096);
        }
#pragma unroll
        for (int np = 0; np < 4; np++) {
            int brow = nj * 64 + (np * 2 + (mt >> 1)) * 8 + rr;
            uint32_t boff = (uint32_t)(((st * 4 + 2) * 2048 +
                brow * 16 + ((mt & 1) ^ ((brow >> 2) & 1)) * 8) * 2);
            uint32_t r[4];
            ldsm4(r, smb + boff);
            bh[2 * np][0] = r[0]; bh[2 * np][1] = r[1];
            bh[2 * np + 1][0] = r[2]; bh[2 * np + 1][1] = r[3];
            ldsm4(r, smb + boff + 4096);
            bl[2 * np][0] = r[0]; bl[2 * np][1] = r[1];
            bl[2 * np + 1][0] = r[2]; bl[2 * np + 1][1] = r[3];
        }
#pragma unroll
        for (int s = 0; s < 2; s++)
#pragma unroll
            for (int nt = 0; nt < 8; nt++) {
                mma16816(acc[s][nt], ah[s], bh[nt][0], bh[nt][1]);
                mma16816(acc[s][nt], ah[s], bl[nt][0], bl[nt][1]);
                mma16816(acc[s][nt], al[s], bh[nt][0], bh[nt][1]);
            }
        if (kk + 1 < K16) STS((kk + 1) & 1);
        __syncthreads();
    }

#pragma unroll
    for (int s = 0; s < 2; s++) {
        int m = m0 + mi * 32 + s * 16 + (lane >> 2);
#pragma unroll
        for (int nt = 0; nt < 8; nt++) {
            int n = n0 + nj * 64 + nt * 8 + 2 * (lane & 3);
            float b0v = bias[n], b1v = bias[n + 1];
            *(float2*)&C[(ull)m * G4 + n] =
                make_float2(acc[s][nt][0] + b0v, acc[s][nt][1] + b1v);
            *(float2*)&C[(ull)(m + 8) * G4 + n] =
                make_float2(acc[s][nt][2] + b0v, acc[s][nt][3] + b1v);
        }
    }
}

// ============================================================================
// LSTM recurrence: K-split, 512 threads (4 warps/SMSP), 64 CTAs, 8-CTA cluster.
// Warps 0-7 handle k-tiles 0-7, warps 8-15 handle k-tiles 8-15; partial D in
// PRE[2] planes, summed in the gate phase (which also adds xg).
// Bfrag slot = (rank*64 + lane*2 + tau) per hi/lo plane -> LDS.128 kt-pairs.
// ============================================================================
#define RT_CL 8

__global__ __launch_bounds__(512, 1) __cluster_dims__(RT_CL, 1, 1)
void lstm_recur_ks(const float* __restrict__ xg, const float* __restrict__ Whh,
                   uint32_t* __restrict__ hs)
{
    __shared__ ull Bfrag[2][2][512];           // [parity][hi/lo][q*64 + lane*2 + tau]
    __shared__ float PRE[2][8][132];           // [khalf][b][ri]
    __shared__ unsigned short stg2[2][8][32];  // [hi/lo][b][u]
    __shared__ __align__(8) ull bars[2];

    int t = threadIdx.x;
    int w = t >> 5, lane = t & 31;
    int kh = w >> 3, wm = w & 7;
    uint32_t rank;
    asm("mov.u32 %0, %%cluster_ctarank;" : "=r"(rank));
    int b0 = (blockIdx.x / RT_CL) * 8;

    uint32_t barsb = smem_u32(bars);
    if (t == 0) {
        asm volatile("mbarrier.init.shared.b64 [%0], %1;" :: "r"(barsb),     "r"(256) : "memory");
        asm volatile("mbarrier.init.shared.b64 [%0], %1;" :: "r"(barsb + 8), "r"(256) : "memory");
    }

    // A fragments for this warp's 8 k-tiles
    int r0 = 16 * wm + (lane >> 2);
    int k0 = (lane & 3) * 2;
    uint32_t ahi[8][4], alo[8][4];
    {
        int g0 = r0 & 3, u0 = r0 >> 2;
        const float* W0 = Whh + (ull)(256 * g0 + 32 * (int)rank + u0) * H_;
        const float* W1 = W0 + 2 * H_;
#pragma unroll
        for (int j = 0; j < 8; j++) {
            int kt = kh * 8 + j;
            sp2(*(const float2*)(W0 + k0 + 16 * kt),     ahi[j][0], alo[j][0]);
            sp2(*(const float2*)(W1 + k0 + 16 * kt),     ahi[j][1], alo[j][1]);
            sp2(*(const float2*)(W0 + k0 + 16 * kt + 8), ahi[j][2], alo[j][2]);
            sp2(*(const float2*)(W1 + k0 + 16 * kt + 8), ahi[j][3], alo[j][3]);
        }
    }
    for (int i = t; i < 2048; i += 512) ((ull*)Bfrag)[i] = 0ull;
    __syncthreads();
    asm volatile("barrier.cluster.arrive.aligned;" ::: "memory");
    asm volatile("barrier.cluster.wait.aligned;" ::: "memory");

    // pusher identity (t<256): target CTA = warp id, piece (b, cq)
    int tgt = w;                       // only used when t < 256
    int pb = t & 7, pcq = (t >> 3) & 3;
    uint32_t rBf = 0, rBar = 0;
    if (t < 256) {
        asm("mapa.shared::cluster.u32 %0, %1, %2;" : "=r"(rBf)  : "r"(smem_u32(Bfrag)), "r"(tgt));
        asm("mapa.shared::cluster.u32 %0, %1, %2;" : "=r"(rBar) : "r"(barsb),           "r"(tgt));
    }

    float c_reg = 0.f;
    int jown = 32 * (int)rank + lane;                 // gates: u=lane, b=w (t<256)
    const float* xgp = xg + (ull)(b0 + w) * T_ * G4 + jown;   // + g*256 per gate

    int ph0 = 0, ph1 = 0;

    for (int ts = 0; ts < T_; ts++) {
        int p = ts & 1;
        // gate threads prefetch xg before the wait (independent of peers)
        float xc0 = 0.f, xc1 = 0.f, xc2 = 0.f, xc3 = 0.f;
        if (t < 256) {
            const float* xpp = xgp + (ull)ts * G4;
            xc0 = xpp[0]; xc1 = xpp[256]; xc2 = xpp[512]; xc3 = xpp[768];
        }
        if (ts) {
            if (p) { mbar_wait_acqc(barsb + 8, ph1); ph1 ^= 1; }
            else   { mbar_wait_acqc(barsb,     ph0); ph0 ^= 1; }
        }

        // 24 mma over this warp's 8 k-tiles (3 chains x 8 deep)
        float aA[4] = {0, 0, 0, 0}, aB[4] = {0, 0, 0, 0}, aC[4] = {0, 0, 0, 0};
        const longlong2* Bh = (const longlong2*)&Bfrag[p][0][0] + (kh * 4) * 32 + lane;
        const longlong2* Bl = (const longlong2*)&Bfrag[p][1][0] + (kh * 4) * 32 + lane;
#pragma unroll
        for (int qq = 0; qq < 4; qq++) {
            longlong2 vh = Bh[qq * 32];
            longlong2 vl = Bl[qq * 32];
            ull bh0v = (ull)vh.x, bh1v = (ull)vh.y;
            ull bl0v = (ull)vl.x, bl1v = (ull)vl.y;
            int j = 2 * qq;
            mma16816(aA, ahi[j], (uint32_t)bh0v, (uint32_t)(bh0v >> 32));
            mma16816(aB, ahi[j], (uint32_t)bl0v, (uint32_t)(bl0v >> 32));
            mma16816(aC, alo[j], (uint32_t)bh0v, (uint32_t)(bh0v >> 32));
            mma16816(aA, ahi[j + 1], (uint32_t)bh1v, (uint32_t)(bh1v >> 32));
            mma16816(aB, ahi[j + 1], (uint32_t)bl1v, (uint32_t)(bl1v >> 32));
            mma16816(aC, alo[j + 1], (uint32_t)bh1v, (uint32_t)(bh1v >> 32));
        }
        PRE[kh][k0][r0]         = aA[0] + aB[0] + aC[0];
        PRE[kh][k0 + 1][r0]     = aA[1] + aB[1] + aC[1];
        PRE[kh][k0][r0 + 8]     = aA[2] + aB[2] + aC[2];
        PRE[kh][k0 + 1][r0 + 8] = aA[3] + aB[3] + aC[3];
        __syncthreads();

        // gates: thread (u=lane, b=w), t<256; sum both K-halves + xg
        if (t < 256) {
            float4 v0 = *(const float4*)&PRE[0][w][4 * lane];
            float4 v1 = *(const float4*)&PRE[1][w][4 * lane];
            float gi = v0.x + v1.x + xc0;
            float gf = v0.y + v1.y + xc1;
            float gg = v0.z + v1.z + xc2;
            float go = v0.w + v1.w + xc3;
            float iv = sigm_f(gi), fv = sigm_f(gf), ov = sigm_f(go);
            float gv = tanh_f(gg);
            c_reg = fv * c_reg + iv * gv;
            float h = ov * tanh_f(c_reg);
            __nv_bfloat16 hh = __float2bfloat16(h);
            __nv_bfloat16 hl = __float2bfloat16(h - __bfloat162float(hh));
            unsigned short uh = __bfloat16_as_ushort(hh);
            unsigned short ul = __bfloat16_as_ushort(hl);
            hs[((ull)(b0 + w) * T_ + ts) * H_ + jown] =
                (uint32_t)uh | ((uint32_t)ul << 16);
            stg2[0][w][lane] = uh;
            stg2[1][w][lane] = ul;
        }
        __syncthreads();

        // push fragment u64 pairs into target CTA's Bfrag[p^1]
        if (t < 256) {
            uint32_t base = rBf + (uint32_t)((p ^ 1) * 8192);
            uint32_t slotb = (uint32_t)((rank * 64 + (4 * pb + pcq) * 2) * 8);
#pragma unroll
            for (int arr = 0; arr < 2; arr++) {
#pragma unroll
                for (int tau = 0; tau < 2; tau++) {
                    uint32_t lo32 = *(const uint32_t*)&stg2[arr][pb][16 * tau + 2 * pcq];
                    uint32_t hi32 = *(const uint32_t*)&stg2[arr][pb][16 * tau + 2 * pcq + 8];
                    ull v = (ull)lo32 | ((ull)hi32 << 32);
                    uint32_t dst = base + (uint32_t)(arr * 4096) + slotb + (uint32_t)(tau * 8);
                    asm volatile("st.shared::cluster.u64 [%0], %1;" :: "r"(dst), "l"(v) : "memory");
                }
            }
            asm volatile("mbarrier.arrive.release.cluster.shared::cluster.b64 _, [%0];"
                         :: "r"(rBar + (uint32_t)((p ^ 1) * 8)) : "memory");
        }
    }

    asm volatile("barrier.cluster.arrive.aligned;" ::: "memory");
    asm volatile("barrier.cluster.wait.aligned;" ::: "memory");
}

// ============================================================================
// FC head (reads packed h)
// ============================================================================
__global__ __launch_bounds__(128) void fc_head(
    const uint32_t* __restrict__ hall, const float* __restrict__ W1,
    const float* __restrict__ b1,     const float* __restrict__ W2,
    const float* __restrict__ b2,     float* __restrict__ out)
{
    __shared__ float hl[H_];
    __shared__ float z[128];
    int b = blockIdx.x, t = threadIdx.x;
    hl[t]       = ups(hall[((ull)b * T_ + (T_ - 1)) * H_ + t]);
    hl[t + 128] = ups(hall[((ull)b * T_ + (T_ - 1)) * H_ + t + 128]);
    __syncthreads();
    float acc = b1[t];
    const float* ww = W1 + t * H_;
#pragma unroll 8
    for (int k = 0; k < H_; k++) acc += ww[k] * hl[k];
    z[t] = fmaxf(acc, 0.f);
    __syncthreads();
    if (t < NC_) {
        float a2 = b2[t];
        const float* w2 = W2 + t * 128;
#pragma unroll 8
        for (int k = 0; k < 128; k++) a2 += w2[k] * z[k];
        out[b * NC_ + t] = a2;
    }
}

// ============================================================================
extern "C" void kernel_launch(void* const* d_in, const int* in_sizes, int n_in,
                              void* d_out, int out_size)
{
    const float* x    = (const float*)d_in[0];
    const float* Wih0 = (const float*)d_in[1];
    const float* Whh0 = (const float*)d_in[2];
    const float* b0   = (const float*)d_in[3];
    const float* Wih1 = (const float*)d_in[4];
    const float* Whh1 = (const float*)d_in[5];
    const float* b1   = (const float*)d_in[6];
    const float* Wih2 = (const float*)d_in[7];
    const float* Whh2 = (const float*)d_in[8];
    const float* b2   = (const float*)d_in[9];
    const float* W1   = (const float*)d_in[10];
    const float* bfc1 = (const float*)d_in[11];
    const float* W2   = (const float*)d_in[12];
    const float* bfc2 = (const float*)d_in[13];
    float* out = (float*)d_out;

    float* xg; uint32_t *as, *hs1, *hs2, *ws;
    cudaGetSymbolAddress((void**)&xg,  g_xg);
    cudaGetSymbolAddress((void**)&as,  g_as);
    cudaGetSymbolAddress((void**)&hs1, g_hs1);
    cudaGetSymbolAddress((void**)&hs2, g_hs2);
    cudaGetSymbolAddress((void**)&ws,  g_ws);

    dim3 ggrd(G4 / 128, (B_ * T_) / 128);   // (8, 256)
    int rgrid = (B_ / 8) * RT_CL;           // 64 CTAs = 8 clusters
    int nx  = B_ * T_ * IN_ / 4;
    int nw0 = G4 * IN_ / 4;
    int nwh = G4 * H_ / 4;

    // layer 0
    split_ps<<<(nx + 255) / 256, 256>>>(x, as, nx);
    split_ps<<<(nw0 + 255) / 256, 256>>>(Wih0, ws, nw0);
    gemm_tc<<<ggrd, 256>>>(as, ws, b0, xg, IN_);
    lstm_recur_ks<<<rgrid, 512>>>(xg, Whh0, hs1);
    // layer 1
    split_ps<<<(nwh + 255) / 256, 256>>>(Wih1, ws, nwh);
    gemm_tc<<<ggrd, 256>>>(hs1, ws, b1, xg, H_);
    lstm_recur_ks<<<rgrid, 512>>>(xg, Whh1, hs2);
    // layer 2
    split_ps<<<(nwh + 255) / 256, 256>>>(Wih2, ws, nwh);
    gemm_tc<<<ggrd, 256>>>(hs2, ws, b2, xg, H_);
    lstm_recur_ks<<<rgrid, 512>>>(xg, Whh2, hs1);
    // head
    fc_head<<<B_, 128>>>(hs1, W1, bfc1, W2, bfc2, out);
}

// round 15
// speedup vs baseline: 1.5062x; 1.4344x over previous
#include <cuda_runtime.h>
#include <cuda_bf16.h>
#include <cstdint>

#define B_   64
#define T_   512
#define IN_  1024
#define H_   256
#define G4   1024
#define NC_  8

typedef unsigned long long ull;

// ---- scratch (device globals; no allocation allowed) ----
__device__ float    g_xg[B_ * T_ * G4];    // gate preactivations fp32
__device__ uint32_t g_as[B_ * T_ * IN_];   // split-packed x
__device__ uint32_t g_hs1[B_ * T_ * H_];   // split-packed h (layer outs)
__device__ uint32_t g_hs2[B_ * T_ * H_];
__device__ uint32_t g_ws[G4 * IN_];        // split-packed Wih (reused per layer)

__device__ __forceinline__ uint32_t smem_u32(const void* p) {
    uint32_t a;
    asm("{ .reg .u64 t; cvta.to.shared.u64 t, %1; cvt.u32.u64 %0, t; }" : "=r"(a) : "l"(p));
    return a;
}
__device__ __forceinline__ uint32_t prmt(uint32_t a, uint32_t b, uint32_t s) {
    uint32_t r; asm("prmt.b32 %0,%1,%2,%3;" : "=r"(r) : "r"(a), "r"(b), "r"(s)); return r;
}
__device__ __forceinline__ uint32_t ps32(float f) {   // packed split bf16
    __nv_bfloat16 h = __float2bfloat16(f);
    __nv_bfloat16 l = __float2bfloat16(f - __bfloat162float(h));
    return (uint32_t)__bfloat16_as_ushort(h) | ((uint32_t)__bfloat16_as_ushort(l) << 16);
}
__device__ __forceinline__ float ups(uint32_t v) {
    return __bfloat162float(__ushort_as_bfloat16((unsigned short)(v & 0xFFFF)))
         + __bfloat162float(__ushort_as_bfloat16((unsigned short)(v >> 16)));
}

// ---- MUFU-free exp / rcp ----
__device__ __forceinline__ float fexp(float x) {
    float z = x * 1.4426950408889634f;
    float t = z + 12582912.0f;
    int n = __float_as_int(t) - 0x4B400000;
    float f = z - (t - 12582912.0f);
    float p = 1.5403530394e-4f;
    p = fmaf(p, f, 1.3333558147e-3f);
    p = fmaf(p, f, 9.6181291891e-3f);
    p = fmaf(p, f, 5.5504108665e-2f);
    p = fmaf(p, f, 2.4022650696e-1f);
    p = fmaf(p, f, 6.9314718056e-1f);
    p = fmaf(p, f, 1.0f);
    return __int_as_float(__float_as_int(p) + (n << 23));
}
__device__ __forceinline__ float frcp(float d) {
    float r = __int_as_float(0x7EF311C3 - __float_as_int(d));
    r = r * fmaf(-d, r, 2.0f);
    r = r * fmaf(-d, r, 2.0f);
    r = r * fmaf(-d, r, 2.0f);
    return r;
}
__device__ __forceinline__ float sigm_f(float x) {
    float xx = fminf(fmaxf(x, -15.f), 15.f);
    return frcp(1.0f + fexp(-xx));
}
__device__ __forceinline__ float tanh_f(float x) {
    float xx = fminf(fmaxf(x, -8.f), 8.f);
    return fmaf(-2.0f, frcp(fexp(2.0f * xx) + 1.0f), 1.0f);
}

__device__ __forceinline__ void mma16816(float* d, const uint32_t* a,
                                         uint32_t b0, uint32_t b1) {
    asm volatile(
        "mma.sync.aligned.m16n8k16.row.col.f32.bf16.bf16.f32 "
        "{%0,%1,%2,%3}, {%4,%5,%6,%7}, {%8,%9}, {%0,%1,%2,%3};"
        : "+f"(d[0]), "+f"(d[1]), "+f"(d[2]), "+f"(d[3])
        : "r"(a[0]), "r"(a[1]), "r"(a[2]), "r"(a[3]), "r"(b0), "r"(b1));
}
__device__ __forceinline__ void ldsm4(uint32_t* r, uint32_t addr) {
    asm volatile("ldmatrix.sync.aligned.m8n8.x4.shared.b16 {%0,%1,%2,%3}, [%4];"
                 : "=r"(r[0]), "=r"(r[1]), "=r"(r[2]), "=r"(r[3]) : "r"(addr));
}
__device__ __forceinline__ void sp2(float2 f, uint32_t& hi, uint32_t& lo) {
    __nv_bfloat162 h = __float22bfloat162_rn(f);
    float2 hf = __bfloat1622float2(h);
    __nv_bfloat162 l = __float22bfloat162_rn(make_float2(f.x - hf.x, f.y - hf.y));
    hi = *(uint32_t*)&h; lo = *(uint32_t*)&l;
}
__device__ __forceinline__ void mbar_wait_acqc(uint32_t a, int ph) {
    asm volatile("{\n\t.reg .pred P;\n\tW%=:\n\t"
                 "mbarrier.try_wait.parity.acquire.cluster.shared::cta.b64 P, [%0], %1;\n\t"
                 "@!P bra W%=;\n\t}" :: "r"(a), "r"(ph) : "memory");
}

// ============================================================================
// split pre-pass: fp32 -> packed split bf16 (hi | lo<<16)
// ============================================================================
__global__ __launch_bounds__(256) void split_ps(const float* __restrict__ in,
                                                uint32_t* __restrict__ out, int n4) {
    int i = blockIdx.x * 256 + threadIdx.x;
    if (i < n4) {
        float4 v = ((const float4*)in)[i];
        uint4 o;
        o.x = ps32(v.x); o.y = ps32(v.y); o.z = ps32(v.z); o.w = ps32(v.w);
        ((uint4*)out)[i] = o;
    }
}

// ============================================================================
// Tensor GEMM (swizzled SMEM — verified; from R12)
// ============================================================================
__global__ __launch_bounds__(256) void gemm_tc(
    const uint32_t* __restrict__ A, const uint32_t* __restrict__ W,
    const float* __restrict__ bias, float* __restrict__ C, int K)
{
    __shared__ __align__(16) unsigned short sm[2][4][128 * 16];
    int t = threadIdx.x, lane = t & 31, w = t >> 5;
    int m0 = blockIdx.y * 128, n0 = blockIdx.x * 128;
    int mi = w & 3, nj = w >> 2;
    int K16 = K / 16;

    int row = t >> 1, half = t & 1;
    const uint32_t* gA = A + (ull)(m0 + row) * K + half * 8;
    const uint32_t* gW = W + (ull)(n0 + row) * K + half * 8;

    uint4 ra0, ra1, rw0, rw1;
    auto LDG = [&](int kk) {
        const uint32_t* pa = gA + kk * 16;
        const uint32_t* pw = gW + kk * 16;
        ra0 = *(const uint4*)pa; ra1 = *(const uint4*)(pa + 4);
        rw0 = *(const uint4*)pw; rw1 = *(const uint4*)(pw + 4);
    };
    auto STS = [&](int st) {
        uint32_t p[8] = { ra0.x, ra0.y, ra0.z, ra0.w, ra1.x, ra1.y, ra1.z, ra1.w };
        uint32_t q[8] = { rw0.x, rw0.y, rw0.z, rw0.w, rw1.x, rw1.y, rw1.z, rw1.w };
        uint4 ahi, alo, whi, wlo;
        ahi.x = prmt(p[0], p[1], 0x5410); alo.x = prmt(p[0], p[1], 0x7632);
        ahi.y = prmt(p[2], p[3], 0x5410); alo.y = prmt(p[2], p[3], 0x7632);
        ahi.z = prmt(p[4], p[5], 0x5410); alo.z = prmt(p[4], p[5], 0x7632);
        ahi.w = prmt(p[6], p[7], 0x5410); alo.w = prmt(p[6], p[7], 0x7632);
        whi.x = prmt(q[0], q[1], 0x5410); wlo.x = prmt(q[0], q[1], 0x7632);
        whi.y = prmt(q[2], q[3], 0x5410); wlo.y = prmt(q[2], q[3], 0x7632);
        whi.z = prmt(q[4], q[5], 0x5410); wlo.z = prmt(q[4], q[5], 0x7632);
        whi.w = prmt(q[6], q[7], 0x5410); wlo.w = prmt(q[6], q[7], 0x7632);
        int o = row * 16 + (half ^ ((row >> 2) & 1)) * 8;
        *(uint4*)&sm[st][0][o] = ahi; *(uint4*)&sm[st][1][o] = alo;
        *(uint4*)&sm[st][2][o] = whi; *(uint4*)&sm[st][3][o] = wlo;
    };

    float acc[2][8][4];
#pragma unroll
    for (int s = 0; s < 2; s++)
#pragma unroll
        for (int nt = 0; nt < 8; nt++)
#pragma unroll
            for (int j = 0; j < 4; j++) acc[s][nt][j] = 0.f;

    uint32_t smb = smem_u32(sm);
    int mt = lane >> 3, rr = lane & 7;

    LDG(0); STS(0);
    __syncthreads();

    for (int kk = 0; kk < K16; kk++) {
        if (kk + 1 < K16) LDG(kk + 1);
        int st = kk & 1;
        uint32_t ah[2][4], al[2][4], bh[8][2], bl[8][2];
#pragma unroll
        for (int s = 0; s < 2; s++) {
            int arow = mi * 32 + s * 16 + (mt & 1) * 8 + rr;
            uint32_t aoff = (uint32_t)(((st * 4 + 0) * 2048 +
                arow * 16 + ((mt >> 1) ^ ((arow >> 2) & 1)) * 8) * 2);
            ldsm4(ah[s], smb + aoff);
            ldsm4(al[s], smb + aoff + 4096);
        }
#pragma unroll
        for (int np = 0; np < 4; np++) {
            int brow = nj * 64 + (np * 2 + (mt >> 1)) * 8 + rr;
            uint32_t boff = (uint32_t)(((st * 4 + 2) * 2048 +
                brow * 16 + ((mt & 1) ^ ((brow >> 2) & 1)) * 8) * 2);
            uint32_t r[4];
            ldsm4(r, smb + boff);
            bh[2 * np][0] = r[0]; bh[2 * np][1] = r[1];
            bh[2 * np + 1][0] = r[2]; bh[2 * np + 1][1] = r[3];
            ldsm4(r, smb + boff + 4096);
            bl[2 * np][0] = r[0]; bl[2 * np][1] = r[1];
            bl[2 * np + 1][0] = r[2]; bl[2 * np + 1][1] = r[3];
        }
#pragma unroll
        for (int s = 0; s < 2; s++)
#pragma unroll
            for (int nt = 0; nt < 8; nt++) {
                mma16816(acc[s][nt], ah[s], bh[nt][0], bh[nt][1]);
                mma16816(acc[s][nt], ah[s], bl[nt][0], bl[nt][1]);
                mma16816(acc[s][nt], al[s], bh[nt][0], bh[nt][1]);
            }
        if (kk + 1 < K16) STS((kk + 1) & 1);
        __syncthreads();
    }

#pragma unroll
    for (int s = 0; s < 2; s++) {
        int m = m0 + mi * 32 + s * 16 + (lane >> 2);
#pragma unroll
        for (int nt = 0; nt < 8; nt++) {
            int n = n0 + nj * 64 + nt * 8 + 2 * (lane & 3);
            float b0v = bias[n], b1v = bias[n + 1];
            *(float2*)&C[(ull)m * G4 + n] =
                make_float2(acc[s][nt][0] + b0v, acc[s][nt][1] + b1v);
            *(float2*)&C[(ull)(m + 8) * G4 + n] =
                make_float2(acc[s][nt][2] + b0v, acc[s][nt][3] + b1v);
        }
    }
}

// ============================================================================
// LSTM recurrence (R7 proven structure; 6 accumulator chains of depth 8).
// 8 clusters x 8 CTAs x 256 thr; CTA rank owns units [32r,32r+32).
// ============================================================================
#define RT_CL 8

__global__ __launch_bounds__(256, 1) __cluster_dims__(RT_CL, 1, 1)
void lstm_recur_mma(const float* __restrict__ xg, const float* __restrict__ Whh,
                    uint32_t* __restrict__ hs)
{
    __shared__ ull Bfrag[2][2][512];              // [parity][hi/lo][kt*32 + 4b+cq]
    __shared__ float PRE[8 * 132];                // [b][ri] pitch 132
    __shared__ unsigned short stg2[2][8][32];     // [hi/lo][b][u]
    __shared__ __align__(8) ull bars[2];

    int t = threadIdx.x;
    int w = t >> 5, lane = t & 31;
    uint32_t rank;
    asm("mov.u32 %0, %%cluster_ctarank;" : "=r"(rank));
    int b0 = (blockIdx.x / RT_CL) * 8;

    uint32_t barsb = smem_u32(bars);
    if (t == 0) {
        asm volatile("mbarrier.init.shared.b64 [%0], %1;" :: "r"(barsb),     "r"(256) : "memory");
        asm volatile("mbarrier.init.shared.b64 [%0], %1;" :: "r"(barsb + 8), "r"(256) : "memory");
    }

    // A fragments (hi/lo) in registers
    int r0 = 16 * w + (lane >> 2);
    int k0 = (lane & 3) * 2;
    uint32_t ahi[16][4], alo[16][4];
    {
        int g0 = r0 & 3, u0 = r0 >> 2;
        const float* W0 = Whh + (ull)(256 * g0 + 32 * (int)rank + u0) * H_;
        const float* W1 = W0 + 2 * H_;
#pragma unroll
        for (int kt = 0; kt < 16; kt++) {
            sp2(*(const float2*)(W0 + k0 + 16 * kt),     ahi[kt][0], alo[kt][0]);
            sp2(*(const float2*)(W1 + k0 + 16 * kt),     ahi[kt][1], alo[kt][1]);
            sp2(*(const float2*)(W0 + k0 + 16 * kt + 8), ahi[kt][2], alo[kt][2]);
            sp2(*(const float2*)(W1 + k0 + 16 * kt + 8), ahi[kt][3], alo[kt][3]);
        }
    }
    for (int i = t; i < 1024; i += 256) ((ull*)Bfrag[0])[i] = 0ull;   // h=0 frags
    __syncthreads();
    asm volatile("barrier.cluster.arrive.aligned;" ::: "memory");
    asm volatile("barrier.cluster.wait.aligned;" ::: "memory");

    // pusher identity: tgt CTA, (b, cq)
    int tgt = t >> 5;
    int pb = t & 7, pcq = (t >> 3) & 3;
    uint32_t rBf, rBar;
    asm("mapa.shared::cluster.u32 %0, %1, %2;" : "=r"(rBf)  : "r"(smem_u32(Bfrag)), "r"(tgt));
    asm("mapa.shared::cluster.u32 %0, %1, %2;" : "=r"(rBar) : "r"(barsb),           "r"(tgt));

    float c_reg = 0.f;
    int jown = 32 * (int)rank + lane;

    int grow0 = 256 * (r0 & 3) + 32 * (int)rank + (r0 >> 2);
    const float* xp0 = xg + (ull)(b0 + k0) * T_ * G4 + grow0;
    const float* xp1 = xg + (ull)(b0 + k0 + 1) * T_ * G4 + grow0;

    int ph0 = 0, ph1 = 0;

    for (int ts = 0; ts < T_; ts++) {
        int p = ts & 1;
        if (ts) {
            if (p) { mbar_wait_acqc(barsb + 8, ph1); ph1 ^= 1; }
            else   { mbar_wait_acqc(barsb,     ph0); ph0 ^= 1; }
        }
        float x00 = xp0[0], x02 = xp0[2], x01 = xp1[0], x03 = xp1[2];
        xp0 += G4; xp1 += G4;

        // 48 mma in 6 independent chains of depth 8 (even/odd kt)
        float aA[2][4] = {{0,0,0,0},{0,0,0,0}};
        float aB[2][4] = {{0,0,0,0},{0,0,0,0}};
        float aC[2][4] = {{0,0,0,0},{0,0,0,0}};
#pragma unroll
        for (int kt = 0; kt < 16; kt++) {
            int e = kt & 1;
            ull bh = Bfrag[p][0][kt * 32 + lane];
            ull bl = Bfrag[p][1][kt * 32 + lane];
            uint32_t bh0 = (uint32_t)bh, bh1 = (uint32_t)(bh >> 32);
            uint32_t bl0 = (uint32_t)bl, bl1 = (uint32_t)(bl >> 32);
            mma16816(aA[e], ahi[kt], bh0, bh1);
            mma16816(aB[e], ahi[kt], bl0, bl1);
            mma16816(aC[e], alo[kt], bh0, bh1);
        }
        PRE[(k0)     * 132 + r0]     = aA[0][0] + aA[1][0] + aB[0][0] + aB[1][0] + aC[0][0] + aC[1][0] + x00;
        PRE[(k0 + 1) * 132 + r0]     = aA[0][1] + aA[1][1] + aB[0][1] + aB[1][1] + aC[0][1] + aC[1][1] + x01;
        PRE[(k0)     * 132 + r0 + 8] = aA[0][2] + aA[1][2] + aB[0][2] + aB[1][2] + aC[0][2] + aC[1][2] + x02;
        PRE[(k0 + 1) * 132 + r0 + 8] = aA[0][3] + aA[1][3] + aB[0][3] + aB[1][3] + aC[0][3] + aC[1][3] + x03;
        __syncthreads();

        // gates: thread = (u=lane, b=w)
        {
            float4 v = *(const float4*)&PRE[w * 132 + 4 * lane];
            float iv = sigm_f(v.x), fv = sigm_f(v.y), ov = sigm_f(v.w);
            float gv = tanh_f(v.z);
            c_reg = fv * c_reg + iv * gv;
            float h = ov * tanh_f(c_reg);
            __nv_bfloat16 hh = __float2bfloat16(h);
            __nv_bfloat16 hl = __float2bfloat16(h - __bfloat162float(hh));
            unsigned short uh = __bfloat16_as_ushort(hh);
            unsigned short ul = __bfloat16_as_ushort(hl);
            hs[((ull)(b0 + w) * T_ + ts) * H_ + jown] =
                (uint32_t)uh | ((uint32_t)ul << 16);
            stg2[0][w][lane] = uh;
            stg2[1][w][lane] = ul;
        }
        __syncthreads();

        // push direct-fragment u64s into target CTA's Bfrag[p^1]
        {
            uint32_t base = rBf + (uint32_t)((p ^ 1) * 8192);
#pragma unroll
            for (int arr = 0; arr < 2; arr++)
#pragma unroll
                for (int tau = 0; tau < 2; tau++) {
                    uint32_t lo32 = *(const uint32_t*)&stg2[arr][pb][16 * tau + 2 * pcq];
                    uint32_t hi32 = *(const uint32_t*)&stg2[arr][pb][16 * tau + 2 * pcq + 8];
                    ull v = (ull)lo32 | ((ull)hi32 << 32);
                    uint32_t idx = (uint32_t)((2 * (int)rank + tau) * 32 + 4 * pb + pcq);
                    uint32_t dst = base + (uint32_t)(arr * 4096) + idx * 8;
                    asm volatile("st.shared::cluster.u64 [%0], %1;" :: "r"(dst), "l"(v) : "memory");
                }
            asm volatile("mbarrier.arrive.release.cluster.shared::cluster.b64 _, [%0];"
                         :: "r"(rBar + (uint32_t)((p ^ 1) * 8)) : "memory");
        }
    }

    asm volatile("barrier.cluster.arrive.aligned;" ::: "memory");
    asm volatile("barrier.cluster.wait.aligned;" ::: "memory");
}

// ============================================================================
// FC head (reads packed h)
// ============================================================================
__global__ __launch_bounds__(128) void fc_head(
    const uint32_t* __restrict__ hall, const float* __restrict__ W1,
    const float* __restrict__ b1,     const float* __restrict__ W2,
    const float* __restrict__ b2,     float* __restrict__ out)
{
    __shared__ float hl[H_];
    __shared__ float z[128];
    int b = blockIdx.x, t = threadIdx.x;
    hl[t]       = ups(hall[((ull)b * T_ + (T_ - 1)) * H_ + t]);
    hl[t + 128] = ups(hall[((ull)b * T_ + (T_ - 1)) * H_ + t + 128]);
    __syncthreads();
    float acc = b1[t];
    const float* ww = W1 + t * H_;
#pragma unroll 8
    for (int k = 0; k < H_; k++) acc += ww[k] * hl[k];
    z[t] = fmaxf(acc, 0.f);
    __syncthreads();
    if (t < NC_) {
        float a2 = b2[t];
        const float* w2 = W2 + t * 128;
#pragma unroll 8
        for (int k = 0; k < 128; k++) a2 += w2[k] * z[k];
        out[b * NC_ + t] = a2;
    }
}

// ============================================================================
extern "C" void kernel_launch(void* const* d_in, const int* in_sizes, int n_in,
                              void* d_out, int out_size)
{
    const float* x    = (const float*)d_in[0];
    const float* Wih0 = (const float*)d_in[1];
    const float* Whh0 = (const float*)d_in[2];
    const float* b0   = (const float*)d_in[3];
    const float* Wih1 = (const float*)d_in[4];
    const float* Whh1 = (const float*)d_in[5];
    const float* b1   = (const float*)d_in[6];
    const float* Wih2 = (const float*)d_in[7];
    const float* Whh2 = (const float*)d_in[8];
    const float* b2   = (const float*)d_in[9];
    const float* W1   = (const float*)d_in[10];
    const float* bfc1 = (const float*)d_in[11];
    const float* W2   = (const float*)d_in[12];
    const float* bfc2 = (const float*)d_in[13];
    float* out = (float*)d_out;

    float* xg; uint32_t *as, *hs1, *hs2, *ws;
    cudaGetSymbolAddress((void**)&xg,  g_xg);
    cudaGetSymbolAddress((void**)&as,  g_as);
    cudaGetSymbolAddress((void**)&hs1, g_hs1);
    cudaGetSymbolAddress((void**)&hs2, g_hs2);
    cudaGetSymbolAddress((void**)&ws,  g_ws);

    dim3 ggrd(G4 / 128, (B_ * T_) / 128);   // (8, 256)
    int rgrid = (B_ / 8) * RT_CL;           // 64 CTAs = 8 clusters
    int nx  = B_ * T_ * IN_ / 4;
    int nw0 = G4 * IN_ / 4;
    int nwh = G4 * H_ / 4;

    // layer 0
    split_ps<<<(nx + 255) / 256, 256>>>(x, as, nx);
    split_ps<<<(nw0 + 255) / 256, 256>>>(Wih0, ws, nw0);
    gemm_tc<<<ggrd, 256>>>(as, ws, b0, xg, IN_);
    lstm_recur_mma<<<rgrid, 256>>>(xg, Whh0, hs1);
    // layer 1
    split_ps<<<(nwh + 255) / 256, 256>>>(Wih1, ws, nwh);
    gemm_tc<<<ggrd, 256>>>(hs1, ws, b1, xg, H_);
    lstm_recur_mma<<<rgrid, 256>>>(xg, Whh1, hs2);
    // layer 2
    split_ps<<<(nwh + 255) / 256, 256>>>(Wih2, ws, nwh);
    gemm_tc<<<ggrd, 256>>>(hs2, ws, b2, xg, H_);
    lstm_recur_mma<<<rgrid, 256>>>(xg, Whh2, hs1);
    // head
    fc_head<<<B_, 128>>>(hs1, W1, bfc1, W2, bfc2, out);
}

// round 16
// speedup vs baseline: 1.9178x; 1.2733x over previous
#include <cuda_runtime.h>
#include <cuda_bf16.h>
#include <cstdint>

#define B_   64
#define T_   512
#define IN_  1024
#define H_   256
#define G4   1024
#define NC_  8

typedef unsigned long long ull;

// ---- scratch (device globals; no allocation allowed) ----
__device__ float    g_xga[B_ * T_ * G4];    // xg buffer A (layers 0, 2)
__device__ float    g_xgb[B_ * T_ * G4];    // xg buffer B (layer 1)
__device__ uint32_t g_as[B_ * T_ * IN_];    // split-packed x
__device__ uint32_t g_hs1[B_ * T_ * H_];    // split-packed h
__device__ uint32_t g_hs2[B_ * T_ * H_];
__device__ uint32_t g_ws0[G4 * IN_];        // split-packed Wih0
__device__ uint32_t g_ws1[G4 * H_];         // split-packed Wih1
__device__ uint32_t g_ws2[G4 * H_];         // split-packed Wih2
__device__ unsigned int g_prog[24];         // per-layer (3) x per-cluster (8)

__device__ __forceinline__ uint32_t smem_u32(const void* p) {
    uint32_t a;
    asm("{ .reg .u64 t; cvta.to.shared.u64 t, %1; cvt.u32.u64 %0, t; }" : "=r"(a) : "l"(p));
    return a;
}
__device__ __forceinline__ uint32_t prmt(uint32_t a, uint32_t b, uint32_t s) {
    uint32_t r; asm("prmt.b32 %0,%1,%2,%3;" : "=r"(r) : "r"(a), "r"(b), "r"(s)); return r;
}
__device__ __forceinline__ uint32_t ps32(float f) {
    __nv_bfloat16 h = __float2bfloat16(f);
    __nv_bfloat16 l = __float2bfloat16(f - __bfloat162float(h));
    return (uint32_t)__bfloat16_as_ushort(h) | ((uint32_t)__bfloat16_as_ushort(l) << 16);
}
__device__ __forceinline__ float ups(uint32_t v) {
    return __bfloat162float(__ushort_as_bfloat16((unsigned short)(v & 0xFFFF)))
         + __bfloat162float(__ushort_as_bfloat16((unsigned short)(v >> 16)));
}

// ---- MUFU-free exp / rcp ----
__device__ __forceinline__ float fexp(float x) {
    float z = x * 1.4426950408889634f;
    float t = z + 12582912.0f;
    int n = __float_as_int(t) - 0x4B400000;
    float f = z - (t - 12582912.0f);
    float p = 1.5403530394e-4f;
    p = fmaf(p, f, 1.3333558147e-3f);
    p = fmaf(p, f, 9.6181291891e-3f);
    p = fmaf(p, f, 5.5504108665e-2f);
    p = fmaf(p, f, 2.4022650696e-1f);
    p = fmaf(p, f, 6.9314718056e-1f);
    p = fmaf(p, f, 1.0f);
    return __int_as_float(__float_as_int(p) + (n << 23));
}
__device__ __forceinline__ float frcp(float d) {
    float r = __int_as_float(0x7EF311C3 - __float_as_int(d));
    r = r * fmaf(-d, r, 2.0f);
    r = r * fmaf(-d, r, 2.0f);
    r = r * fmaf(-d, r, 2.0f);
    return r;
}
__device__ __forceinline__ float sigm_f(float x) {
    float xx = fminf(fmaxf(x, -15.f), 15.f);
    return frcp(1.0f + fexp(-xx));
}
__device__ __forceinline__ float tanh_f(float x) {
    float xx = fminf(fmaxf(x, -8.f), 8.f);
    return fmaf(-2.0f, frcp(fexp(2.0f * xx) + 1.0f), 1.0f);
}

__device__ __forceinline__ void mma16816(float* d, const uint32_t* a,
                                         uint32_t b0, uint32_t b1) {
    asm volatile(
        "mma.sync.aligned.m16n8k16.row.col.f32.bf16.bf16.f32 "
        "{%0,%1,%2,%3}, {%4,%5,%6,%7}, {%8,%9}, {%0,%1,%2,%3};"
        : "+f"(d[0]), "+f"(d[1]), "+f"(d[2]), "+f"(d[3])
        : "r"(a[0]), "r"(a[1]), "r"(a[2]), "r"(a[3]), "r"(b0), "r"(b1));
}
__device__ __forceinline__ void ldsm4(uint32_t* r, uint32_t addr) {
    asm volatile("ldmatrix.sync.aligned.m8n8.x4.shared.b16 {%0,%1,%2,%3}, [%4];"
                 : "=r"(r[0]), "=r"(r[1]), "=r"(r[2]), "=r"(r[3]) : "r"(addr));
}
__device__ __forceinline__ void sp2(float2 f, uint32_t& hi, uint32_t& lo) {
    __nv_bfloat162 h = __float22bfloat162_rn(f);
    float2 hf = __bfloat1622float2(h);
    __nv_bfloat162 l = __float22bfloat162_rn(make_float2(f.x - hf.x, f.y - hf.y));
    hi = *(uint32_t*)&h; lo = *(uint32_t*)&l;
}
__device__ __forceinline__ void mbar_wait_acqc(uint32_t a, int ph) {
    asm volatile("{\n\t.reg .pred P;\n\tW%=:\n\t"
                 "mbarrier.try_wait.parity.acquire.cluster.shared::cta.b64 P, [%0], %1;\n\t"
                 "@!P bra W%=;\n\t}" :: "r"(a), "r"(ph) : "memory");
}

// ============================================================================
__global__ void zero_prog(unsigned int* p) {
    if (threadIdx.x < 24) p[threadIdx.x] = 0;
}

__global__ __launch_bounds__(256) void split_ps(const float* __restrict__ in,
                                                uint32_t* __restrict__ out, int n4) {
    int i = blockIdx.x * 256 + threadIdx.x;
    if (i < n4) {
        float4 v = ((const float4*)in)[i];
        uint4 o;
        o.x = ps32(v.x); o.y = ps32(v.y); o.z = ps32(v.z); o.w = ps32(v.w);
        ((uint4*)out)[i] = o;
    }
}

// ============================================================================
// GEMM inner body (shared by standalone + fused). smf points at 32KB buffer.
// C[M,1024] = A[M,K](ps32) @ W[1024,K](ps32)^T + bias. m0/n0 given.
// ============================================================================
__device__ __forceinline__ void gemm_body(
    const uint32_t* __restrict__ A, const uint32_t* __restrict__ W,
    const float* __restrict__ bias, float* __restrict__ C,
    int K, int m0, int n0, unsigned short* smf, int t)
{
    int lane = t & 31, w = t >> 5;
    int mi = w & 3, nj = w >> 2;
    int K16 = K / 16;

    int row = t >> 1, half = t & 1;
    const uint32_t* gA = A + (ull)(m0 + row) * K + half * 8;
    const uint32_t* gW = W + (ull)(n0 + row) * K + half * 8;

    uint4 ra0, ra1, rw0, rw1;
    auto LDG = [&](int kk) {
        const uint32_t* pa = gA + kk * 16;
        const uint32_t* pw = gW + kk * 16;
        ra0 = *(const uint4*)pa; ra1 = *(const uint4*)(pa + 4);
        rw0 = *(const uint4*)pw; rw1 = *(const uint4*)(pw + 4);
    };
    auto STS = [&](int st) {
        uint32_t p[8] = { ra0.x, ra0.y, ra0.z, ra0.w, ra1.x, ra1.y, ra1.z, ra1.w };
        uint32_t q[8] = { rw0.x, rw0.y, rw0.z, rw0.w, rw1.x, rw1.y, rw1.z, rw1.w };
        uint4 ahi, alo, whi, wlo;
        ahi.x = prmt(p[0], p[1], 0x5410); alo.x = prmt(p[0], p[1], 0x7632);
        ahi.y = prmt(p[2], p[3], 0x5410); alo.y = prmt(p[2], p[3], 0x7632);
        ahi.z = prmt(p[4], p[5], 0x5410); alo.z = prmt(p[4], p[5], 0x7632);
        ahi.w = prmt(p[6], p[7], 0x5410); alo.w = prmt(p[6], p[7], 0x7632);
        whi.x = prmt(q[0], q[1], 0x5410); wlo.x = prmt(q[0], q[1], 0x7632);
        whi.y = prmt(q[2], q[3], 0x5410); wlo.y = prmt(q[2], q[3], 0x7632);
        whi.z = prmt(q[4], q[5], 0x5410); wlo.z = prmt(q[4], q[5], 0x7632);
        whi.w = prmt(q[6], q[7], 0x5410); wlo.w = prmt(q[6], q[7], 0x7632);
        int o = row * 16 + (half ^ ((row >> 2) & 1)) * 8;
        *(uint4*)&smf[(st * 4 + 0) * 2048 + o] = ahi;
        *(uint4*)&smf[(st * 4 + 1) * 2048 + o] = alo;
        *(uint4*)&smf[(st * 4 + 2) * 2048 + o] = whi;
        *(uint4*)&smf[(st * 4 + 3) * 2048 + o] = wlo;
    };

    float acc[2][8][4];
#pragma unroll
    for (int s = 0; s < 2; s++)
#pragma unroll
        for (int nt = 0; nt < 8; nt++)
#pragma unroll
            for (int j = 0; j < 4; j++) acc[s][nt][j] = 0.f;

    uint32_t smb = smem_u32(smf);
    int mt = lane >> 3, rr = lane & 7;

    LDG(0); STS(0);
    __syncthreads();

    for (int kk = 0; kk < K16; kk++) {
        if (kk + 1 < K16) LDG(kk + 1);
        int st = kk & 1;
        uint32_t ah[2][4], al[2][4], bh[8][2], bl[8][2];
#pragma unroll
        for (int s = 0; s < 2; s++) {
            int arow = mi * 32 + s * 16 + (mt & 1) * 8 + rr;
            uint32_t aoff = (uint32_t)(((st * 4 + 0) * 2048 +
                arow * 16 + ((mt >> 1) ^ ((arow >> 2) & 1)) * 8) * 2);
            ldsm4(ah[s], smb + aoff);
            ldsm4(al[s], smb + aoff + 4096);
        }
#pragma unroll
        for (int np = 0; np < 4; np++) {
            int brow = nj * 64 + (np * 2 + (mt >> 1)) * 8 + rr;
            uint32_t boff = (uint32_t)(((st * 4 + 2) * 2048 +
                brow * 16 + ((mt & 1) ^ ((brow >> 2) & 1)) * 8) * 2);
            uint32_t r[4];
            ldsm4(r, smb + boff);
            bh[2 * np][0] = r[0]; bh[2 * np][1] = r[1];
            bh[2 * np + 1][0] = r[2]; bh[2 * np + 1][1] = r[3];
            ldsm4(r, smb + boff + 4096);
            bl[2 * np][0] = r[0]; bl[2 * np][1] = r[1];
            bl[2 * np + 1][0] = r[2]; bl[2 * np + 1][1] = r[3];
        }
#pragma unroll
        for (int s = 0; s < 2; s++)
#pragma unroll
            for (int nt = 0; nt < 8; nt++) {
                mma16816(acc[s][nt], ah[s], bh[nt][0], bh[nt][1]);
                mma16816(acc[s][nt], ah[s], bl[nt][0], bl[nt][1]);
                mma16816(acc[s][nt], al[s], bh[nt][0], bh[nt][1]);
            }
        if (kk + 1 < K16) STS((kk + 1) & 1);
        __syncthreads();
    }

#pragma unroll
    for (int s = 0; s < 2; s++) {
        int m = m0 + mi * 32 + s * 16 + (lane >> 2);
#pragma unroll
        for (int nt = 0; nt < 8; nt++) {
            int n = n0 + nj * 64 + nt * 8 + 2 * (lane & 3);
            float b0v = bias[n], b1v = bias[n + 1];
            *(float2*)&C[(ull)m * G4 + n] =
                make_float2(acc[s][nt][0] + b0v, acc[s][nt][1] + b1v);
            *(float2*)&C[(ull)(m + 8) * G4 + n] =
                make_float2(acc[s][nt][2] + b0v, acc[s][nt][3] + b1v);
        }
    }
}

// standalone GEMM (layer 0, K=1024) at occupancy 2
__global__ __launch_bounds__(256, 2) void gemm_tc(
    const uint32_t* __restrict__ A, const uint32_t* __restrict__ W,
    const float* __restrict__ bias, float* __restrict__ C, int K)
{
    __shared__ __align__(16) unsigned short smf[2 * 4 * 2048];
    gemm_body(A, W, bias, C, K, blockIdx.y * 128, blockIdx.x * 128,
              smf, threadIdx.x);
}

// ============================================================================
// Fused kernel: blockIdx 0..63 = recurrence clusters (layer l);
// blockIdx >= 64  = GEMM tiles of layer l+1, spinning on progress counters.
// ============================================================================
#define RT_CL 8

__global__ __launch_bounds__(256, 1) __cluster_dims__(RT_CL, 1, 1)
void fused_rg(const float* __restrict__ xg, const float* __restrict__ Whh,
              uint32_t* __restrict__ hs,
              const uint32_t* __restrict__ wsW, const float* __restrict__ biasN,
              float* __restrict__ xg_out, unsigned int* __restrict__ prog)
{
    __shared__ __align__(16) char smbuf[32768];
    __shared__ __align__(8) ull bars[2];

    int t = threadIdx.x;

    if (blockIdx.x >= 64) {
        // ---------------- GEMM side (layer l+1), t-ascending tile order ----
        int bid2 = blockIdx.x - 64;
        int idx = bid2 >> 3, nblk = bid2 & 7;
        int batch = idx & 63, tblk = idx >> 6;
        unsigned int need = 8u * (unsigned)(tblk * 128 + 128);
        if (t == 0) {
            unsigned int v;
            do {
                asm volatile("ld.acquire.gpu.global.u32 %0, [%1];"
                             : "=r"(v) : "l"(prog + (batch >> 3)) : "memory");
                if (v < need) __nanosleep(256);
            } while (v < need);
        }
        __syncthreads();
        gemm_body(hs, wsW, biasN, xg_out, H_,
                  batch * T_ + tblk * 128, nblk * 128,
                  (unsigned short*)smbuf, t);
        return;
    }

    // ---------------- recurrence side (layer l) ----------------
    ull*   Bf   = (ull*)smbuf;                          // [p][arr][512]: p*1024+arr*512+i
    float* PRE  = (float*)(smbuf + 16384);              // [b][ri] pitch 132
    unsigned short* stg2 = (unsigned short*)(smbuf + 16384 + 4224);  // [2][8][32]

    int w = t >> 5, lane = t & 31;
    uint32_t rank;
    asm("mov.u32 %0, %%cluster_ctarank;" : "=r"(rank));
    int b0 = (blockIdx.x / RT_CL) * 8;

    uint32_t barsb = smem_u32(bars);
    if (t == 0) {
        asm volatile("mbarrier.init.shared.b64 [%0], %1;" :: "r"(barsb),     "r"(256) : "memory");
        asm volatile("mbarrier.init.shared.b64 [%0], %1;" :: "r"(barsb + 8), "r"(256) : "memory");
    }

    int r0 = 16 * w + (lane >> 2);
    int k0 = (lane & 3) * 2;
    uint32_t ahi[16][4], alo[16][4];
    {
        int g0 = r0 & 3, u0 = r0 >> 2;
        const float* W0 = Whh + (ull)(256 * g0 + 32 * (int)rank + u0) * H_;
        const float* W1 = W0 + 2 * H_;
#pragma unroll
        for (int kt = 0; kt < 16; kt++) {
            sp2(*(const float2*)(W0 + k0 + 16 * kt),     ahi[kt][0], alo[kt][0]);
            sp2(*(const float2*)(W1 + k0 + 16 * kt),     ahi[kt][1], alo[kt][1]);
            sp2(*(const float2*)(W0 + k0 + 16 * kt + 8), ahi[kt][2], alo[kt][2]);
            sp2(*(const float2*)(W1 + k0 + 16 * kt + 8), ahi[kt][3], alo[kt][3]);
        }
    }
    for (int i = t; i < 1024; i += 256) Bf[i] = 0ull;   // parity-0 frags (h=0)
    __syncthreads();
    asm volatile("barrier.cluster.arrive.aligned;" ::: "memory");
    asm volatile("barrier.cluster.wait.aligned;" ::: "memory");

    int tgt = t >> 5;
    int pb = t & 7, pcq = (t >> 3) & 3;
    uint32_t rBf, rBar;
    asm("mapa.shared::cluster.u32 %0, %1, %2;" : "=r"(rBf)  : "r"(smem_u32(smbuf)), "r"(tgt));
    asm("mapa.shared::cluster.u32 %0, %1, %2;" : "=r"(rBar) : "r"(barsb),           "r"(tgt));

    float c_reg = 0.f;
    int jown = 32 * (int)rank + lane;
    unsigned int* myprog = prog + (blockIdx.x >> 3);

    int grow0 = 256 * (r0 & 3) + 32 * (int)rank + (r0 >> 2);
    const float* xp0 = xg + (ull)(b0 + k0) * T_ * G4 + grow0;
    const float* xp1 = xg + (ull)(b0 + k0 + 1) * T_ * G4 + grow0;

    int ph0 = 0, ph1 = 0;

    for (int ts = 0; ts < T_; ts++) {
        int p = ts & 1;
        // prefetch xg BEFORE the wait (overlap DRAM with barrier latency)
        float x00 = xp0[0], x02 = xp0[2], x01 = xp1[0], x03 = xp1[2];
        xp0 += G4; xp1 += G4;
        if (ts) {
            if (p) { mbar_wait_acqc(barsb + 8, ph1); ph1 ^= 1; }
            else   { mbar_wait_acqc(barsb,     ph0); ph0 ^= 1; }
        }

        // 48 mma in 6 chains of depth 8
        float aA[2][4] = {{0,0,0,0},{0,0,0,0}};
        float aB[2][4] = {{0,0,0,0},{0,0,0,0}};
        float aC[2][4] = {{0,0,0,0},{0,0,0,0}};
#pragma unroll
        for (int kt = 0; kt < 16; kt++) {
            int e = kt & 1;
            ull bh = Bf[p * 1024 + kt * 32 + lane];
            ull bl = Bf[p * 1024 + 512 + kt * 32 + lane];
            uint32_t bh0 = (uint32_t)bh, bh1 = (uint32_t)(bh >> 32);
            uint32_t bl0 = (uint32_t)bl, bl1 = (uint32_t)(bl >> 32);
            mma16816(aA[e], ahi[kt], bh0, bh1);
            mma16816(aB[e], ahi[kt], bl0, bl1);
            mma16816(aC[e], alo[kt], bh0, bh1);
        }
        PRE[(k0)     * 132 + r0]     = aA[0][0] + aA[1][0] + aB[0][0] + aB[1][0] + aC[0][0] + aC[1][0] + x00;
        PRE[(k0 + 1) * 132 + r0]     = aA[0][1] + aA[1][1] + aB[0][1] + aB[1][1] + aC[0][1] + aC[1][1] + x01;
        PRE[(k0)     * 132 + r0 + 8] = aA[0][2] + aA[1][2] + aB[0][2] + aB[1][2] + aC[0][2] + aC[1][2] + x02;
        PRE[(k0 + 1) * 132 + r0 + 8] = aA[0][3] + aA[1][3] + aB[0][3] + aB[1][3] + aC[0][3] + aC[1][3] + x03;
        __syncthreads();

        {   // gates: thread = (u=lane, b=w)
            float4 v = *(const float4*)&PRE[w * 132 + 4 * lane];
            float iv = sigm_f(v.x), fv = sigm_f(v.y), ov = sigm_f(v.w);
            float gv = tanh_f(v.z);
            c_reg = fv * c_reg + iv * gv;
            float h = ov * tanh_f(c_reg);
            __nv_bfloat16 hh = __float2bfloat16(h);
            __nv_bfloat16 hl = __float2bfloat16(h - __bfloat162float(hh));
            unsigned short uh = __bfloat16_as_ushort(hh);
            unsigned short ul = __bfloat16_as_ushort(hl);
            hs[((ull)(b0 + w) * T_ + ts) * H_ + jown] =
                (uint32_t)uh | ((uint32_t)ul << 16);
            stg2[(0 * 8 + w) * 32 + lane] = uh;
            stg2[(1 * 8 + w) * 32 + lane] = ul;
        }
        __syncthreads();

        // publish progress (h of this CTA for step ts is globally visible)
        if (t == 0)
            asm volatile("red.release.gpu.global.add.u32 [%0], 1;"
                         :: "l"(myprog) : "memory");

        {   // push direct-fragment u64s into target CTA's Bfrag[p^1]
            uint32_t base = rBf + (uint32_t)((p ^ 1) * 8192);
#pragma unroll
            for (int arr = 0; arr < 2; arr++)
#pragma unroll
                for (int tau = 0; tau < 2; tau++) {
                    uint32_t lo32 = *(const uint32_t*)&stg2[(arr * 8 + pb) * 32 + 16 * tau + 2 * pcq];
                    uint32_t hi32 = *(const uint32_t*)&stg2[(arr * 8 + pb) * 32 + 16 * tau + 2 * pcq + 8];
                    ull v = (ull)lo32 | ((ull)hi32 << 32);
                    uint32_t idx = (uint32_t)((2 * (int)rank + tau) * 32 + 4 * pb + pcq);
                    uint32_t dst = base + (uint32_t)(arr * 4096) + idx * 8;
                    asm volatile("st.shared::cluster.u64 [%0], %1;" :: "r"(dst), "l"(v) : "memory");
                }
            asm volatile("mbarrier.arrive.release.cluster.shared::cluster.b64 _, [%0];"
                         :: "r"(rBar + (uint32_t)((p ^ 1) * 8)) : "memory");
        }
    }

    asm volatile("barrier.cluster.arrive.aligned;" ::: "memory");
    asm volatile("barrier.cluster.wait.aligned;" ::: "memory");
}

// ============================================================================
__global__ __launch_bounds__(128) void fc_head(
    const uint32_t* __restrict__ hall, const float* __restrict__ W1,
    const float* __restrict__ b1,     const float* __restrict__ W2,
    const float* __restrict__ b2,     float* __restrict__ out)
{
    __shared__ float hl[H_];
    __shared__ float z[128];
    int b = blockIdx.x, t = threadIdx.x;
    hl[t]       = ups(hall[((ull)b * T_ + (T_ - 1)) * H_ + t]);
    hl[t + 128] = ups(hall[((ull)b * T_ + (T_ - 1)) * H_ + t + 128]);
    __syncthreads();
    float acc = b1[t];
    const float* ww = W1 + t * H_;
#pragma unroll 8
    for (int k = 0; k < H_; k++) acc += ww[k] * hl[k];
    z[t] = fmaxf(acc, 0.f);
    __syncthreads();
    if (t < NC_) {
        float a2 = b2[t];
        const float* w2 = W2 + t * 128;
#pragma unroll 8
        for (int k = 0; k < 128; k++) a2 += w2[k] * z[k];
        out[b * NC_ + t] = a2;
    }
}

// ============================================================================
extern "C" void kernel_launch(void* const* d_in, const int* in_sizes, int n_in,
                              void* d_out, int out_size)
{
    const float* x    = (const float*)d_in[0];
    const float* Wih0 = (const float*)d_in[1];
    const float* Whh0 = (const float*)d_in[2];
    const float* b0   = (const float*)d_in[3];
    const float* Wih1 = (const float*)d_in[4];
    const float* Whh1 = (const float*)d_in[5];
    const float* b1   = (const float*)d_in[6];
    const float* Wih2 = (const float*)d_in[7];
    const float* Whh2 = (const float*)d_in[8];
    const float* b2   = (const float*)d_in[9];
    const float* W1   = (const float*)d_in[10];
    const float* bfc1 = (const float*)d_in[11];
    const float* W2   = (const float*)d_in[12];
    const float* bfc2 = (const float*)d_in[13];
    float* out = (float*)d_out;

    float *xga, *xgb; uint32_t *as, *hs1, *hs2, *ws0, *ws1, *ws2;
    unsigned int* prog;
    cudaGetSymbolAddress((void**)&xga, g_xga);
    cudaGetSymbolAddress((void**)&xgb, g_xgb);
    cudaGetSymbolAddress((void**)&as,  g_as);
    cudaGetSymbolAddress((void**)&hs1, g_hs1);
    cudaGetSymbolAddress((void**)&hs2, g_hs2);
    cudaGetSymbolAddress((void**)&ws0, g_ws0);
    cudaGetSymbolAddress((void**)&ws1, g_ws1);
    cudaGetSymbolAddress((void**)&ws2, g_ws2);
    cudaGetSymbolAddress((void**)&prog, g_prog);

    dim3 ggrd(G4 / 128, (B_ * T_) / 128);   // (8, 256) — layer-0 GEMM
    int fgrid = 64 + 2048;                  // recurrence + gemm tiles
    int nx  = B_ * T_ * IN_ / 4;
    int nw0 = G4 * IN_ / 4;
    int nwh = G4 * H_ / 4;

    zero_prog<<<1, 32>>>(prog);
    split_ps<<<(nx + 255) / 256, 256>>>(x, as, nx);
    split_ps<<<(nw0 + 255) / 256, 256>>>(Wih0, ws0, nw0);
    split_ps<<<(nwh + 255) / 256, 256>>>(Wih1, ws1, nwh);
    split_ps<<<(nwh + 255) / 256, 256>>>(Wih2, ws2, nwh);

    // layer 0 gemm (occ 2)
    gemm_tc<<<ggrd, 256>>>(as, ws0, b0, xga, IN_);
    // layer0 recurrence + layer1 gemm overlapped
    fused_rg<<<fgrid, 256>>>(xga, Whh0, hs1, ws1, b1, xgb, prog + 0);
    // layer1 recurrence + layer2 gemm overlapped
    fused_rg<<<fgrid, 256>>>(xgb, Whh1, hs2, ws2, b2, xga, prog + 8);
    // layer2 recurrence only
    fused_rg<<<64, 256>>>(xga, Whh2, hs1, ws2, b2, xgb, prog + 16);
    // head
    fc_head<<<B_, 128>>>(hs1, W1, bfc1, W2, bfc2, out);
}